// round 11
// baseline (speedup 1.0000x reference)
#include <cuda_runtime.h>
#include <cuda_fp16.h>
#include <math.h>
#include <stdint.h>

// ---------------- problem constants ----------------
#define NB    1000      // B
#define NN    20        // neighbors per node
#define D_    172
#define DT_   100
#define E_    272       // D + DT
#define DK_   444       // D + DT + DE
#define KPAD  448       // padded K for full KV GEMM (layer 2)
#define TEK   288       // padded K for layer-1 te GEMM (100+172 -> 288)
#define HD    136       // head dim (E/2)
#define NKV   544       // fused K|V output width
#define QK    192       // padded K for Q gemm / mem gemm (172->192)
#define OK    288       // padded K for Wo gemm (272->288)
#define CST   288       // CTX row stride (fp16, zero-padded)
#define NNODE 100000

#define R1    (NB*NN)    // 20000 layer-1 queries
#define ROWS1 (R1*NN)    // 400000 layer-1 kv rows

// ---------------- scratch (device globals; zero-initialized, no allocs) ----------------
__device__ __align__(16) __half g_Ah   [(size_t)ROWS1 * TEK];   // te rows (L1)
__device__ __align__(16) __half g_Afull[(size_t)R1 * KPAD];     // layer-2 full KV input + MLP input
__device__ __align__(16) __half g_KVh  [(size_t)ROWS1 * NKV];   // fused K|V output
__device__ __align__(16) __half g_MEMh [(size_t)NNODE * QK];    // fp16 memory, stride 192 (pads stay 0)
__device__ __align__(16) __half g_MEMKV[(size_t)NNODE * NKV];   // mem @ Wkv_mem (no bias)
__device__ __align__(16) __half g_Qh   [(size_t)R1 * E_];
__device__ __align__(16) __half g_CTXh [(size_t)R1 * CST];      // pad cols 272-287 stay 0
__device__ __align__(16) __half g_SRCh [(size_t)R1 * QK];       // pad cols 172-191 stay 0
__device__ __align__(16) __half g_Hh   [(size_t)R1 * QK];       // pad cols 172-191 stay 0
__device__ __align__(16) __half g_EMBh [(size_t)R1 * D_];
// fp16 weights (padded)
__device__ __align__(16) __half g_Wqh   [(size_t)2 * E_ * QK];
__device__ __align__(16) __half g_WKVm  [(size_t)NKV * QK];     // layer1 mem part  [544][192]
__device__ __align__(16) __half g_WKVte [(size_t)NKV * TEK];    // layer1 te part   [544][288]
__device__ __align__(16) __half g_WKVfull[(size_t)NKV * KPAD];  // layer2 full      [544][448]
__device__ __align__(16) __half g_Woh   [(size_t)2 * E_ * OK];
__device__ __align__(16) __half g_W1h   [(size_t)2 * D_ * KPAD];
__device__ __align__(16) __half g_W2h   [(size_t)2 * D_ * QK];
__device__ float g_bKV  [2 * NKV];
__device__ float g_zero [NKV];          // stays 0
__device__ float g_CQ   [2 * E_];
__device__ int   g_AM   [R1];

// ============================================================================
// fp16 tensor-core GEMM via mma.sync (HMMA) -- round-10 structure, mainloop
// strength-reduced: hoisted LDSM bases, incremental cp.async pointers.
// CTA tile 128x96, BK=32, 256 thr (warps 4m x 2n, warp tile 32x48).
// 3-stage cp.async ring, ONE __syncthreads per chunk.
// ============================================================================
#define AST 40
#define BST 40
#define A_STAGE (128 * AST)                 // halfs
#define B_STAGE (96 * BST)                  // halfs
#define AS_BYTES (A_STAGE * 2)              // 10240
#define BS_BYTES (B_STAGE * 2)              // 7680
#define HG_SMEM ((3 * (A_STAGE + B_STAGE)) * 2)   // 53760 bytes

__device__ __forceinline__ void ldsm_x4(uint32_t* r, uint32_t addr) {
    asm volatile("ldmatrix.sync.aligned.m8n8.x4.shared.b16 {%0,%1,%2,%3}, [%4];"
                 : "=r"(r[0]), "=r"(r[1]), "=r"(r[2]), "=r"(r[3]) : "r"(addr));
}
__device__ __forceinline__ void mma16816(float* d, const uint32_t* a, uint32_t b0, uint32_t b1) {
    asm volatile("mma.sync.aligned.m16n8k16.row.col.f32.f16.f16.f32 "
                 "{%0,%1,%2,%3}, {%4,%5,%6,%7}, {%8,%9}, {%0,%1,%2,%3};"
                 : "+f"(d[0]), "+f"(d[1]), "+f"(d[2]), "+f"(d[3])
                 : "r"(a[0]), "r"(a[1]), "r"(a[2]), "r"(a[3]), "r"(b0), "r"(b1));
}
__device__ __forceinline__ void cp16(uint32_t dst, const void* src, int sz) {
    asm volatile("cp.async.cg.shared.global [%0], [%1], 16, %2;"
                 :: "r"(dst), "l"(src), "r"(sz));
}
__device__ __forceinline__ uint32_t cvta_s(const void* p) {
    return (uint32_t)__cvta_generic_to_shared(p);
}

template<int HALF_OUT, int HAS_ADD>
__global__ __launch_bounds__(256, 3)
void hgemm(const __half* __restrict__ A, int lda,
           const __half* __restrict__ W,
           const float* __restrict__ bias,
           const int* __restrict__ rowzero,
           const __half* __restrict__ addsrc,     // epilogue gather-add (HAS_ADD)
           const int* __restrict__ addidx,
           void* __restrict__ Cout, int ldc,
           int M, int N, int K, int relu)
{
    extern __shared__ __half smem[];
    __half* sA = smem;                       // 3 stages of 128x32
    __half* sB = smem + 3 * A_STAGE;         // 3 stages of 96x32

    const int tid  = threadIdx.x;
    const int lane = tid & 31, wid = tid >> 5;
    const int warp_m = wid & 3, warp_n = wid >> 2;
    const int m0 = blockIdx.y * 128;
    const int n0 = blockIdx.x * 96;
    const int nchunks = K >> 5;

    float acc[2][6][4];
    #pragma unroll
    for (int i = 0; i < 2; i++)
        #pragma unroll
        for (int j = 0; j < 6; j++)
            #pragma unroll
            for (int q = 0; q < 4; q++) acc[i][j][q] = 0.f;

    // ---- hoisted cp.async addressing (per thread) ----
    const int rowL = tid >> 2, segL = tid & 3;
    const __half* gA0 = A + (size_t)(m0 + rowL) * lda + segL * 8;
    const __half* gA1 = gA0 + (size_t)64 * lda;
    const __half* gB0 = W + (size_t)(n0 + rowL) * K + segL * 8;
    const __half* gB1 = gB0 + (size_t)64 * K;
    const int szA0 = (m0 + rowL)      < M ? 16 : 0;
    const int szA1 = (m0 + rowL + 64) < M ? 16 : 0;
    const int szB0 = (n0 + rowL)      < N ? 16 : 0;
    const int szB1 = (n0 + rowL + 64) < N ? 16 : 0;
    const bool doB1 = tid < 128;             // B rows 64..95 only
    const uint32_t dA0 = cvta_s(&sA[rowL * AST + segL * 8]);
    const uint32_t dA1 = dA0 + 64 * AST * 2;
    const uint32_t dB0 = cvta_s(&sB[rowL * BST + segL * 8]);
    const uint32_t dB1 = dB0 + 64 * BST * 2;

    // ---- hoisted LDSM base addresses (per warp lane) ----
    const uint32_t aBase = cvta_s(&sA[(warp_m * 32 + (lane & 15)) * AST + (lane >> 4) * 8]);
    const uint32_t bBase = cvta_s(&sB[(warp_n * 48 + ((lane >> 4) << 3) + (lane & 7)) * BST
                                      + ((lane >> 3) & 1) * 8]);

    auto issueLoads = [&](int s) {
        uint32_t soA = s * AS_BYTES, soB = s * BS_BYTES;
        cp16(dA0 + soA, gA0, szA0);
        cp16(dA1 + soA, gA1, szA1);
        cp16(dB0 + soB, gB0, szB0);
        if (doB1) cp16(dB1 + soB, gB1, szB1);
        gA0 += 32; gA1 += 32; gB0 += 32; gB1 += 32;
    };

    auto computeStage = [&](int s) {
        const uint32_t aS = aBase + s * AS_BYTES;
        const uint32_t bS = bBase + s * BS_BYTES;
        #pragma unroll
        for (int kk = 0; kk < 2; ++kk) {
            uint32_t afr[2][4];
            #pragma unroll
            for (int i = 0; i < 2; ++i)
                ldsm_x4(afr[i], aS + i * (16 * AST * 2) + kk * 32);
            uint32_t bfr[3][4];
            #pragma unroll
            for (int j = 0; j < 3; ++j)
                ldsm_x4(bfr[j], bS + j * (16 * BST * 2) + kk * 32);
            #pragma unroll
            for (int i = 0; i < 2; ++i)
                #pragma unroll
                for (int j = 0; j < 6; ++j)
                    mma16816(acc[i][j], afr[i], bfr[j >> 1][(j & 1) * 2], bfr[j >> 1][(j & 1) * 2 + 1]);
        }
    };

    // prologue: prefetch 2 stages
    issueLoads(0);
    asm volatile("cp.async.commit_group;" ::: "memory");
    if (nchunks > 1) issueLoads(1);
    asm volatile("cp.async.commit_group;" ::: "memory");

    for (int c = 0; c < nchunks; ++c) {
        asm volatile("cp.async.wait_group 1;" ::: "memory");  // stage c ready
        __syncthreads();                                       // buffer (c+2)%3 drained
        if (c + 2 < nchunks) issueLoads((c + 2) % 3);
        asm volatile("cp.async.commit_group;" ::: "memory");   // uniform group accounting
        computeStage(c % 3);
    }

    // ---- epilogue ----
    #pragma unroll
    for (int i = 0; i < 2; ++i) {
        #pragma unroll
        for (int half_ = 0; half_ < 2; ++half_) {
            int r = m0 + warp_m * 32 + i * 16 + (lane >> 2) + half_ * 8;
            if (r >= M) continue;
            int rz = rowzero ? rowzero[r] : 0;
            const __half* arow = HAS_ADD ? addsrc + (size_t)addidx[r] * ldc : nullptr;
            #pragma unroll
            for (int j = 0; j < 6; ++j) {
                int col = n0 + warp_n * 48 + j * 8 + (lane & 3) * 2;
                if (col < N) {
                    float v0 = acc[i][j][half_ * 2]     + bias[col];
                    float v1 = acc[i][j][half_ * 2 + 1] + bias[col + 1];
                    if (HAS_ADD) {
                        float2 af = __half22float2(*(const __half2*)(arow + col));
                        v0 += af.x; v1 += af.y;
                    }
                    if (rz) { v0 = 0.f; v1 = 0.f; }
                    if (relu) { v0 = fmaxf(v0, 0.f); v1 = fmaxf(v1, 0.f); }
                    if (HALF_OUT) {
                        *(__half2*)((__half*)Cout + (size_t)r * ldc + col) =
                            __floats2half2_rn(v0, v1);
                    } else {
                        float* cp = (float*)Cout + (size_t)r * ldc + col;
                        cp[0] = v0; cp[1] = v1;
                    }
                }
            }
        }
    }
}

// ---------------- fused weight conversion: one launch, static job table ----------------
struct CvtJob { int srcSel; long srcOff; int N; int Ksrc; int koff; int Kcopy; int KP; int dstSel; long dstOff; };
__constant__ CvtJob c_jobs[14] = {
    {0, 0,                 E_, E_,  0,   D_,  QK,   0, 0},                 // Wq l0
    {0, (long)E_*E_,       E_, E_,  0,   D_,  QK,   0, (long)E_*QK},       // Wq l1
    {1, 0,                 E_, DK_, 0,   D_,  QK,   1, 0},                 // Wk mem (l0)
    {2, 0,                 E_, DK_, 0,   D_,  QK,   1, (long)E_*QK},       // Wv mem (l0)
    {1, 0,                 E_, DK_, D_,  272, TEK,  2, 0},                 // Wk te  (l0)
    {2, 0,                 E_, DK_, D_,  272, TEK,  2, (long)E_*TEK},      // Wv te  (l0)
    {1, (long)E_*DK_,      E_, DK_, 0,   DK_, KPAD, 3, 0},                 // Wk full (l1)
    {2, (long)E_*DK_,      E_, DK_, 0,   DK_, KPAD, 3, (long)E_*KPAD},     // Wv full (l1)
    {3, 0,                 E_, E_,  0,   E_,  OK,   4, 0},                 // Wo l0
    {3, (long)E_*E_,       E_, E_,  0,   E_,  OK,   4, (long)E_*OK},       // Wo l1
    {4, 0,                 D_, DK_, 0,   DK_, KPAD, 5, 0},                 // W1 l0
    {4, (long)D_*DK_,      D_, DK_, 0,   DK_, KPAD, 5, (long)D_*KPAD},     // W1 l1
    {5, 0,                 D_, D_,  0,   D_,  QK,   6, 0},                 // W2 l0
    {5, (long)D_*D_,       D_, D_,  0,   D_,  QK,   6, (long)D_*QK},       // W2 l1
};

__global__ void convert_all(const float* __restrict__ Wq, const float* __restrict__ Wk,
                            const float* __restrict__ Wv, const float* __restrict__ Wo,
                            const float* __restrict__ W1, const float* __restrict__ W2)
{
    CvtJob j = c_jobs[blockIdx.y];
    const float* srcTab[6] = {Wq, Wk, Wv, Wo, W1, W2};
    __half* dstTab[7] = {g_Wqh, g_WKVm, g_WKVte, g_WKVfull, g_Woh, g_W1h, g_W2h};
    const float* src = srcTab[j.srcSel] + j.srcOff;
    __half* dst = dstTab[j.dstSel] + j.dstOff;
    long total = (long)j.N * j.KP;
    for (long i = (long)blockIdx.x * blockDim.x + threadIdx.x; i < total;
         i += (long)gridDim.x * blockDim.x) {
        int k = (int)(i % j.KP);
        int n = (int)(i / j.KP);
        dst[i] = __float2half(k < j.Kcopy ? src[(size_t)n * j.Ksrc + j.koff + k] : 0.f);
    }
}

// ---------------- memory -> fp16 (stride QK, pads stay 0) ----------------
__global__ void memconv(const float* __restrict__ mem)
{
    long total = (long)NNODE * D_;
    for (long i = (long)blockIdx.x*blockDim.x + threadIdx.x; i < total;
         i += (long)gridDim.x * blockDim.x) {
        int r = (int)(i / D_);
        int k = (int)(i % D_);
        g_MEMh[(size_t)r * QK + k] = __float2half(mem[i]);
    }
}

// ---------------- fp16 row gather from g_MEMh (both stride QK), uint4 copies ------------
__global__ void gather16(const int* __restrict__ idx, __half* __restrict__ dst, int rows)
{
    long total = (long)rows * 24;   // 24 uint4 per 192-half row
    for (long i = (long)blockIdx.x*blockDim.x + threadIdx.x; i < total;
         i += (long)gridDim.x * blockDim.x) {
        int r = (int)(i / 24);
        int s = (int)(i % 24);
        ((uint4*)(dst + (size_t)r * QK))[s] =
            ((const uint4*)(g_MEMh + (size_t)idx[r] * QK))[s];
    }
}

// ---------------- bias concat for fused KV ----------------
__global__ void concat_bkv(const float* __restrict__ bk, const float* __restrict__ bv)
{
    int l = blockIdx.x, n = threadIdx.x;
    if (n < NKV)
        g_bKV[l * NKV + n] = (n < E_) ? bk[l * E_ + n] : bv[l * E_ + n - E_];
}

// ---------------- constant part of q ----------------
__global__ void cq_kernel(const float* __restrict__ Wq, const float* __restrict__ bq,
                          const float* __restrict__ b_time)
{
    int l = blockIdx.x;
    int n = threadIdx.x;
    if (n < E_) {
        float s = bq[l*E_ + n];
        const float* w = Wq + (size_t)l*E_*E_ + (size_t)n*E_ + D_;
        #pragma unroll 4
        for (int j = 0; j < DT_; j++) s += cosf(b_time[j]) * w[j];
        g_CQ[l*E_ + n] = s;
    }
}

// ---------------- copy SRC into MLP-input cols [272, 444) of g_Afull ----------------
__global__ void copy_src(int rows)
{
    long total = (long)rows * D_;
    for (long i = (long)blockIdx.x*blockDim.x + threadIdx.x; i < total;
         i += (long)gridDim.x * blockDim.x) {
        int r = (int)(i / D_);
        int k = (int)(i % D_);
        g_Afull[(size_t)r * KPAD + E_ + k] = g_SRCh[(size_t)r * QK + k];
    }
}

// ---------------- layer-1 te rows (warp per row): [cos(100) | edge(172) | pad16] -------
__global__ void build_te(const float* __restrict__ edge_features,
                         const int* __restrict__ edge_idxs,
                         const float* __restrict__ edge_times,
                         const float* __restrict__ timestamps,
                         const float* __restrict__ w_time, const float* __restrict__ b_time,
                         int rows)
{
    int warp = threadIdx.x >> 5, lane = threadIdx.x & 31;
    int m = blockIdx.x * 4 + warp;
    if (m >= rows) return;

    __half2* out = (__half2*)(g_Ah + (size_t)m * TEK);
    float dt = timestamps[m / (NN*NN)] - edge_times[m];
    const float* ef = edge_features + (size_t)edge_idxs[m] * D_;

    #pragma unroll
    for (int i = lane; i < TEK/2; i += 32) {
        int k = i * 2;
        float a, b;
        if (k < DT_) {
            a = cosf(dt*w_time[k]   + b_time[k]);
            b = cosf(dt*w_time[k+1] + b_time[k+1]);
        } else if (k < DT_ + D_) {
            a = ef[k - DT_]; b = ef[k - DT_ + 1];
        } else { a = 0.f; b = 0.f; }
        out[i] = __floats2half2_rn(a, b);
    }
}

// ---------------- layer-2 full rows (warp per row): [emb(172)|cos(100)|edge(172)|pad4] --
__global__ void build_full(const __half* __restrict__ memh,
                           const float* __restrict__ edge_features,
                           const int* __restrict__ edge_idxs,
                           const float* __restrict__ edge_times,
                           const float* __restrict__ timestamps,
                           const float* __restrict__ w_time, const float* __restrict__ b_time,
                           int rows)
{
    int warp = threadIdx.x >> 5, lane = threadIdx.x & 31;
    int m = blockIdx.x * 4 + warp;
    if (m >= rows) return;

    __half2* out = (__half2*)(g_Afull + (size_t)m * KPAD);
    const __half* nbh = memh + (size_t)m * D_;
    float dt = timestamps[m / NN] - edge_times[m];
    const float* ef = edge_features + (size_t)edge_idxs[m] * D_;

    #pragma unroll
    for (int i = lane; i < KPAD/2; i += 32) {
        int k = i * 2;
        float a, b;
        if (k < D_) {
            __half2 h = *(const __half2*)(nbh + k); float2 f = __half22float2(h); a = f.x; b = f.y;
        } else if (k < E_) {
            int j = k - D_;
            a = cosf(dt*w_time[j]   + b_time[j]);
            b = cosf(dt*w_time[j+1] + b_time[j+1]);
        } else if (k < DK_) {
            a = ef[k - E_]; b = ef[k - E_ + 1];
        } else { a = 0.f; b = 0.f; }
        out[i] = __floats2half2_rn(a, b);
    }
}

// ---------------- attention: warp per query row, fp16 in/out ----------------
__global__ void attn_kernel(const __half* __restrict__ Q, const __half* __restrict__ KV,
                            const int* __restrict__ nbrs,
                            __half* __restrict__ CTX, int* __restrict__ AM, int R)
{
    __shared__ float qsh[4][E_];
    int warp = threadIdx.x >> 5, lane = threadIdx.x & 31;
    int row = blockIdx.x*4 + warp;
    if (row >= R) return;

    for (int d = lane; d < E_; d += 32)
        qsh[warp][d] = __half2float(Q[(size_t)row*E_ + d]);
    __syncwarp();

    const float scale = rsqrtf((float)HD);
    float a[2][NN];

    #pragma unroll
    for (int h = 0; h < 2; h++) {
        const float* qh = qsh[warp] + h*HD;
        for (int n = 0; n < NN; n++) {
            const __half2* k2 = (const __half2*)(KV + ((size_t)row*NN + n)*NKV + h*HD);
            float s = 0.f;
            for (int i = lane; i < HD/2; i += 32) {
                float2 kf = __half22float2(k2[i]);
                s += qh[2*i]*kf.x + qh[2*i+1]*kf.y;
            }
            #pragma unroll
            for (int o = 16; o; o >>= 1) s += __shfl_xor_sync(0xffffffffu, s, o);
            a[h][n] = s * scale;
        }
    }

    int allm = 1;
    #pragma unroll
    for (int n = 0; n < NN; n++) {
        int nb = nbrs[(size_t)row*NN + n];
        if (nb == 0) { a[0][n] = -1e9f; a[1][n] = -1e9f; }
        else allm = 0;
    }

    #pragma unroll
    for (int h = 0; h < 2; h++) {
        float mx = -3.4e38f;
        #pragma unroll
        for (int n = 0; n < NN; n++) mx = fmaxf(mx, a[h][n]);
        float ssum = 0.f;
        #pragma unroll
        for (int n = 0; n < NN; n++) { float e = expf(a[h][n] - mx); a[h][n] = e; ssum += e; }
        float inv = 1.f / ssum;
        #pragma unroll
        for (int n = 0; n < NN; n++) a[h][n] *= inv;
    }
    if (lane == 0) AM[row] = allm;

    for (int i = lane; i < E_/2; i += 32) {
        int h = (2*i) >= HD;
        float ax = 0.f, ay = 0.f;
        #pragma unroll
        for (int n = 0; n < NN; n++) {
            const __half2* v2 = (const __half2*)(KV + ((size_t)row*NN + n)*NKV + E_);
            float2 vf = __half22float2(v2[i]);
            ax += a[h][n] * vf.x;
            ay += a[h][n] * vf.y;
        }
        *(__half2*)(CTX + (size_t)row*CST + 2*i) = __floats2half2_rn(ax, ay);
    }
}

// ---------------- host helpers ----------------
static void launch_hgemm_h(const __half* A, int lda, const __half* W, const float* bias,
                           const int* rz, __half* C, int ldc, int M, int N, int K, int relu)
{
    dim3 grid((N + 95)/96, (M + 127)/128);
    hgemm<1,0><<<grid, 256, HG_SMEM>>>(A, lda, W, bias, rz, nullptr, nullptr, (void*)C, ldc, M, N, K, relu);
}
static void launch_hgemm_add(const __half* A, int lda, const __half* W, const float* bias,
                             const __half* addsrc, const int* addidx,
                             __half* C, int ldc, int M, int N, int K)
{
    dim3 grid((N + 95)/96, (M + 127)/128);
    hgemm<1,1><<<grid, 256, HG_SMEM>>>(A, lda, W, bias, nullptr, addsrc, addidx, (void*)C, ldc, M, N, K, 0);
}
static void launch_hgemm_f(const __half* A, int lda, const __half* W, const float* bias,
                           const int* rz, float* C, int ldc, int M, int N, int K, int relu)
{
    dim3 grid((N + 95)/96, (M + 127)/128);
    hgemm<0,0><<<grid, 256, HG_SMEM>>>(A, lda, W, bias, rz, nullptr, nullptr, (void*)C, ldc, M, N, K, relu);
}

extern "C" void kernel_launch(void* const* d_in, const int* in_sizes, int n_in,
                              void* d_out, int out_size)
{
    const float* memory = (const float*)d_in[0];
    const float* edgef  = (const float*)d_in[1];
    const int*   srcn   = (const int*)  d_in[2];
    const float* ts     = (const float*)d_in[3];
    const int*   nb1    = (const int*)  d_in[4];
    const int*   ei1    = (const int*)  d_in[5];
    const float* et1    = (const float*)d_in[6];
    const int*   nb2    = (const int*)  d_in[7];
    const int*   ei2    = (const int*)  d_in[8];
    const float* et2    = (const float*)d_in[9];
    const float* w_time = (const float*)d_in[10];
    const float* b_time = (const float*)d_in[11];
    const float* Wq = (const float*)d_in[12];
    const float* bq = (const float*)d_in[13];
    const float* Wk = (const float*)d_in[14];
    const float* bk = (const float*)d_in[15];
    const float* Wv = (const float*)d_in[16];
    const float* bv = (const float*)d_in[17];
    const float* Wo = (const float*)d_in[18];
    const float* bo = (const float*)d_in[19];
    const float* W1 = (const float*)d_in[20];
    const float* b1 = (const float*)d_in[21];
    const float* W2 = (const float*)d_in[22];
    const float* b2 = (const float*)d_in[23];
    float* out = (float*)d_out;

    __half *pAh, *pAfull, *pKVh, *pMEMKV, *pQh, *pCTXh, *pSRCh, *pHh, *pEMBh, *pMEMh;
    __half *pWqh, *pWKVm, *pWKVte, *pWKVfull, *pWoh, *pW1h, *pW2h;
    float *pbKV, *pZero, *pCQ;
    int* pAM;
    cudaGetSymbolAddress((void**)&pAh,     g_Ah);
    cudaGetSymbolAddress((void**)&pAfull,  g_Afull);
    cudaGetSymbolAddress((void**)&pKVh,    g_KVh);
    cudaGetSymbolAddress((void**)&pMEMKV,  g_MEMKV);
    cudaGetSymbolAddress((void**)&pQh,     g_Qh);
    cudaGetSymbolAddress((void**)&pCTXh,   g_CTXh);
    cudaGetSymbolAddress((void**)&pSRCh,   g_SRCh);
    cudaGetSymbolAddress((void**)&pHh,     g_Hh);
    cudaGetSymbolAddress((void**)&pEMBh,   g_EMBh);
    cudaGetSymbolAddress((void**)&pMEMh,   g_MEMh);
    cudaGetSymbolAddress((void**)&pWqh,    g_Wqh);
    cudaGetSymbolAddress((void**)&pWKVm,   g_WKVm);
    cudaGetSymbolAddress((void**)&pWKVte,  g_WKVte);
    cudaGetSymbolAddress((void**)&pWKVfull,g_WKVfull);
    cudaGetSymbolAddress((void**)&pWoh,    g_Woh);
    cudaGetSymbolAddress((void**)&pW1h,    g_W1h);
    cudaGetSymbolAddress((void**)&pW2h,    g_W2h);
    cudaGetSymbolAddress((void**)&pbKV,    g_bKV);
    cudaGetSymbolAddress((void**)&pZero,   g_zero);
    cudaGetSymbolAddress((void**)&pCQ,     g_CQ);
    cudaGetSymbolAddress((void**)&pAM,     g_AM);

    cudaFuncSetAttribute((const void*)hgemm<1,0>, cudaFuncAttributeMaxDynamicSharedMemorySize, HG_SMEM);
    cudaFuncSetAttribute((const void*)hgemm<1,1>, cudaFuncAttributeMaxDynamicSharedMemorySize, HG_SMEM);
    cudaFuncSetAttribute((const void*)hgemm<0,0>, cudaFuncAttributeMaxDynamicSharedMemorySize, HG_SMEM);

    const size_t WQs = (size_t)E_*QK, WOs = (size_t)E_*OK,
                 W1s = (size_t)D_*KPAD, W2s = (size_t)D_*QK;

    convert_all<<<dim3(64, 14), 256>>>(Wq, Wk, Wv, Wo, W1, W2);                  // 1
    memconv<<<512, 256>>>(memory);                                               // 2
    build_te<<<(ROWS1 + 3)/4, 128>>>(edgef, ei2, et2, ts, w_time, b_time, ROWS1);// 3
    // memKV[100000,544] = mem @ Wkv_mem^T  (no bias)
    launch_hgemm_h(pMEMh, QK, pWKVm, pZero, nullptr,                             // 4
                   pMEMKV, NKV, NNODE, NKV, QK, 0);
    concat_bkv<<<2, NKV>>>(bk, bv);                                              // 5
    // KV = te @ Wkv_te^T + bKV + memKV[nb2]
    launch_hgemm_add(pAh, TEK, pWKVte, pbKV, pMEMKV, nb2,                        // 6
                     pKVh, NKV, ROWS1, NKV, TEK);

    cq_kernel<<<2, E_>>>(Wq, bq, b_time);                                        // 7
    gather16<<<(R1*24 + 255)/256, 256>>>(nb1, pSRCh, R1);                        // 8
    launch_hgemm_h(pSRCh, QK, pWqh, pCQ, nullptr, pQh, E_, R1, E_, QK, 0);       // 9

    attn_kernel<<<(R1 + 3)/4, 128>>>(pQh, pKVh, nb2, pCTXh, pAM, R1);            // 10

    launch_hgemm_h(pCTXh, CST, pWoh, bo, pAM, pAfull, KPAD, R1, E_, OK, 0);      // 11
    copy_src<<<(R1*D_ + 255)/256, 256>>>(R1);                                    // 12
    launch_hgemm_h(pAfull, KPAD, pW1h, b1, nullptr, pHh, QK, R1, D_, KPAD, 1);   // 13
    launch_hgemm_h(pHh, QK, pW2h, b2, nullptr, pEMBh, D_, R1, D_, QK, 0);        // 14

    // ================= Layer 2 =================
    gather16<<<(NB*24 + 255)/256, 256>>>(srcn, pSRCh, NB);                       // 15
    launch_hgemm_h(pSRCh, QK, pWqh + WQs, pCQ + E_, nullptr, pQh, E_, NB, E_, QK, 0); // 16

    build_full<<<(R1 + 3)/4, 128>>>(pEMBh, edgef, ei1, et1, ts, w_time, b_time, R1); // 17
    launch_hgemm_h(pAfull, KPAD, pWKVfull, pbKV + NKV, nullptr,
                   pKVh, NKV, R1, NKV, KPAD, 0);                                 // 18

    attn_kernel<<<(NB + 3)/4, 128>>>(pQh, pKVh, nb1, pCTXh, pAM, NB);            // 19

    launch_hgemm_h(pCTXh, CST, pWoh + WOs, bo + E_, pAM, pAfull, KPAD, NB, E_, OK, 0); // 20
    copy_src<<<(NB*D_ + 255)/256, 256>>>(NB);                                    // 21
    launch_hgemm_h(pAfull, KPAD, pW1h + W1s, b1 + D_, nullptr, pHh, QK, NB, D_, KPAD, 1); // 22
    launch_hgemm_f(pHh, QK, pW2h + W2s, b2 + D_, nullptr, out, D_, NB, D_, QK, 0);        // 23
}

// round 12
// speedup vs baseline: 1.4718x; 1.4718x over previous
#include <cuda_runtime.h>
#include <cuda_fp16.h>
#include <math.h>
#include <stdint.h>

// ---------------- problem constants ----------------
#define NB    1000      // B
#define NN    20        // neighbors per node
#define D_    172
#define DT_   100
#define E_    272       // D + DT
#define DK_   444       // D + DT + DE
#define KPAD  448       // padded K for W1 GEMM input
#define QK    192       // padded K for q gemm (172->192)
#define QTK   288       // padded K for q~ gemm (272->288)
#define QTW   912       // QT row stride: [q~0(448) | q~1(448) | c0 c1 | pad]
#define QTN   898       // valid QT cols
#define CTW   896       // CTX row stride: [ctx0(448) | ctx1(448)]
#define WQKR  904       // Wqk rows (padded from 898)
#define NNODE 100000

#define R1    (NB*NN)    // 20000 layer-1 queries
#define ROWS1 (R1*NN)    // 400000 layer-1 kv rows

// ---------------- scratch (device globals; zero-initialized, no allocs) ----------------
__device__ __align__(16) __half g_MEMh [(size_t)NNODE * QK];    // fp16 memory, stride 192
__device__ __align__(16) __half g_SRCh [(size_t)R1 * QK];       // pads stay 0
__device__ __align__(16) __half g_Qh   [(size_t)R1 * E_ + 64];  // +64: K=288 overread pad
__device__ __align__(16) __half g_QTh  [(size_t)R1 * QTW];      // q~ per query
__device__ __align__(16) __half g_CTX  [(size_t)R1 * CTW];      // per-head raw contexts
__device__ __align__(16) __half g_Afull[(size_t)R1 * KPAD];     // [O(272)|src(172)|pad4] MLP input
__device__ __align__(16) __half g_Hh   [(size_t)R1 * QK];       // pads stay 0
__device__ __align__(16) __half g_EMBh [(size_t)R1 * D_ + 64];
// weights
__device__ __align__(16) __half g_Wqh [(size_t)2 * E_ * QK];
__device__ __align__(16) __half g_Wqk [(size_t)2 * WQKR * QTK]; // [898->904][288]
__device__ __align__(16) __half g_Wov [(size_t)2 * E_ * CTW];   // combined Wo@Wv per head
__device__ __align__(16) __half g_W1h [(size_t)2 * D_ * KPAD];
__device__ __align__(16) __half g_W2h [(size_t)2 * D_ * QK];
__device__ float g_bOV  [2 * E_];
__device__ float g_CQ   [2 * E_];
__device__ float g_zero [1024];         // stays 0
__device__ int   g_AM   [R1];

// ============================================================================
// fp16 tensor-core GEMM (HMMA) -- round-10 proven version (1407us baseline):
//   C[M,N] = A[M,K] @ W[N,K]^T + bias   (fp32 accum; fp16/fp32 out, relu, rowzero)
// CTA tile 128x96, BK=32, 256 thr (warps 4m x 2n, warp tile 32x48).
// 3-stage cp.async ring, ONE __syncthreads per chunk.
// ============================================================================
#define AST 40
#define BST 40
#define A_STAGE (128 * AST)
#define B_STAGE (96 * BST)
#define HG_SMEM ((3 * (A_STAGE + B_STAGE)) * 2)   // 53760 bytes

__device__ __forceinline__ void ldsm_x4(uint32_t* r, uint32_t addr) {
    asm volatile("ldmatrix.sync.aligned.m8n8.x4.shared.b16 {%0,%1,%2,%3}, [%4];"
                 : "=r"(r[0]), "=r"(r[1]), "=r"(r[2]), "=r"(r[3]) : "r"(addr));
}
__device__ __forceinline__ void mma16816(float* d, const uint32_t* a, uint32_t b0, uint32_t b1) {
    asm volatile("mma.sync.aligned.m16n8k16.row.col.f32.f16.f16.f32 "
                 "{%0,%1,%2,%3}, {%4,%5,%6,%7}, {%8,%9}, {%0,%1,%2,%3};"
                 : "+f"(d[0]), "+f"(d[1]), "+f"(d[2]), "+f"(d[3])
                 : "r"(a[0]), "r"(a[1]), "r"(a[2]), "r"(a[3]), "r"(b0), "r"(b1));
}
__device__ __forceinline__ void cp16(uint32_t dst, const void* src, int sz) {
    asm volatile("cp.async.cg.shared.global [%0], [%1], 16, %2;"
                 :: "r"(dst), "l"(src), "r"(sz));
}

template<int HALF_OUT>
__global__ __launch_bounds__(256)
void hgemm(const __half* __restrict__ A, int lda,
           const __half* __restrict__ W,
           const float* __restrict__ bias,
           const int* __restrict__ rowzero,
           void* __restrict__ Cout, int ldc,
           int M, int N, int K, int relu)
{
    extern __shared__ __half smem[];
    __half* sA = smem;
    __half* sB = smem + 3 * A_STAGE;

    const int tid  = threadIdx.x;
    const int lane = tid & 31, wid = tid >> 5;
    const int warp_m = wid & 3, warp_n = wid >> 2;
    const int m0 = blockIdx.y * 128;
    const int n0 = blockIdx.x * 96;
    const int nchunks = K >> 5;

    float acc[2][6][4];
    #pragma unroll
    for (int i = 0; i < 2; i++)
        #pragma unroll
        for (int j = 0; j < 6; j++)
            #pragma unroll
            for (int q = 0; q < 4; q++) acc[i][j][q] = 0.f;

    auto loadA = [&](int s, int k0) {
        #pragma unroll
        for (int c = tid; c < 512; c += 256) {
            int row = c >> 2, seg = c & 3;
            int gm = m0 + row;
            uint32_t dst = (uint32_t)__cvta_generic_to_shared(&sA[s * A_STAGE + row * AST + seg * 8]);
            cp16(dst, A + (size_t)gm * lda + k0 + seg * 8, gm < M ? 16 : 0);
        }
    };
    auto loadB = [&](int s, int k0) {
        #pragma unroll
        for (int c = tid; c < 384; c += 256) {
            int row = c >> 2, seg = c & 3;
            int gn = n0 + row;
            uint32_t dst = (uint32_t)__cvta_generic_to_shared(&sB[s * B_STAGE + row * BST + seg * 8]);
            cp16(dst, W + (size_t)gn * K + k0 + seg * 8, gn < N ? 16 : 0);
        }
    };

    auto computeStage = [&](int s) {
        const __half* As = sA + s * A_STAGE;
        const __half* Bs = sB + s * B_STAGE;
        #pragma unroll
        for (int kk = 0; kk < 2; ++kk) {
            uint32_t afr[2][4];
            #pragma unroll
            for (int i = 0; i < 2; ++i) {
                uint32_t addr = (uint32_t)__cvta_generic_to_shared(
                    &As[(warp_m * 32 + i * 16 + (lane & 15)) * AST + kk * 16 + (lane >> 4) * 8]);
                ldsm_x4(afr[i], addr);
            }
            uint32_t bfr[3][4];
            #pragma unroll
            for (int j = 0; j < 3; ++j) {
                int nrow = warp_n * 48 + j * 16 + ((lane >> 4) << 3) + (lane & 7);
                int kcol = kk * 16 + ((lane >> 3) & 1) * 8;
                uint32_t addr = (uint32_t)__cvta_generic_to_shared(&Bs[nrow * BST + kcol]);
                ldsm_x4(bfr[j], addr);
            }
            #pragma unroll
            for (int i = 0; i < 2; ++i)
                #pragma unroll
                for (int j = 0; j < 6; ++j)
                    mma16816(acc[i][j], afr[i], bfr[j >> 1][(j & 1) * 2], bfr[j >> 1][(j & 1) * 2 + 1]);
        }
    };

    loadA(0, 0); loadB(0, 0);
    asm volatile("cp.async.commit_group;" ::: "memory");
    if (nchunks > 1) { loadA(1, 32); loadB(1, 32); }
    asm volatile("cp.async.commit_group;" ::: "memory");

    for (int c = 0; c < nchunks; ++c) {
        asm volatile("cp.async.wait_group 1;" ::: "memory");
        __syncthreads();
        if (c + 2 < nchunks) {
            int s = (c + 2) % 3;
            loadA(s, (c + 2) * 32); loadB(s, (c + 2) * 32);
        }
        asm volatile("cp.async.commit_group;" ::: "memory");
        computeStage(c % 3);
    }

    #pragma unroll
    for (int i = 0; i < 2; ++i) {
        #pragma unroll
        for (int half_ = 0; half_ < 2; ++half_) {
            int r = m0 + warp_m * 32 + i * 16 + (lane >> 2) + half_ * 8;
            if (r >= M) continue;
            int rz = rowzero ? rowzero[r] : 0;
            #pragma unroll
            for (int j = 0; j < 6; ++j) {
                int col = n0 + warp_n * 48 + j * 8 + (lane & 3) * 2;
                if (col < N) {
                    float v0 = acc[i][j][half_ * 2]     + bias[col];
                    float v1 = acc[i][j][half_ * 2 + 1] + bias[col + 1];
                    if (rz) { v0 = 0.f; v1 = 0.f; }
                    if (relu) { v0 = fmaxf(v0, 0.f); v1 = fmaxf(v1, 0.f); }
                    if (HALF_OUT) {
                        *(__half2*)((__half*)Cout + (size_t)r * ldc + col) =
                            __floats2half2_rn(v0, v1);
                    } else {
                        float* cp = (float*)Cout + (size_t)r * ldc + col;
                        cp[0] = v0; cp[1] = v1;
                    }
                }
            }
        }
    }
}

// ---------------- weight conversion jobs (Wq, W1, W2) ----------------
struct CvtJob { int srcSel; long srcOff; int N; int Ksrc; int Kcopy; int KP; int dstSel; long dstOff; };
__constant__ CvtJob c_jobs[6] = {
    {0, 0,            E_, E_,  D_,  QK,   0, 0},
    {0, (long)E_*E_,  E_, E_,  D_,  QK,   0, (long)E_*QK},
    {1, 0,            D_, DK_, DK_, KPAD, 1, 0},
    {1, (long)D_*DK_, D_, DK_, DK_, KPAD, 1, (long)D_*KPAD},
    {2, 0,            D_, D_,  D_,  QK,   2, 0},
    {2, (long)D_*D_,  D_, D_,  D_,  QK,   2, (long)D_*QK},
};

__global__ void convert_all(const float* __restrict__ Wq, const float* __restrict__ W1,
                            const float* __restrict__ W2)
{
    CvtJob j = c_jobs[blockIdx.y];
    const float* srcTab[3] = {Wq, W1, W2};
    __half* dstTab[3] = {g_Wqh, g_W1h, g_W2h};
    const float* src = srcTab[j.srcSel] + j.srcOff;
    __half* dst = dstTab[j.dstSel] + j.dstOff;
    long total = (long)j.N * j.KP;
    for (long i = (long)blockIdx.x * blockDim.x + threadIdx.x; i < total;
         i += (long)gridDim.x * blockDim.x) {
        int k = (int)(i % j.KP);
        int n = (int)(i / j.KP);
        dst[i] = __float2half(k < j.Kcopy ? src[(size_t)n * j.Ksrc + k] : 0.f);
    }
}

// ---------------- Wqk[l][n][k]: transpose-scatter of Wk + bk rows ----------------
// n<444:        k<136        -> Wk[l][k][n]
// 448<=n<892:   136<=k<272   -> Wk[l][k][n-448]
// n==896: c0 row: k<136      -> bk[l][k]
// n==897: c1 row: 136<=k<272 -> bk[l][k]
__global__ void build_wqk(const float* __restrict__ Wk, const float* __restrict__ bk)
{
    int l = blockIdx.y;
    __half* dst = g_Wqk + (size_t)l * WQKR * QTK;
    const long total = (long)WQKR * QTK;
    for (long i = (long)blockIdx.x * blockDim.x + threadIdx.x; i < total;
         i += (long)gridDim.x * blockDim.x) {
        int n = (int)(i / QTK), k = (int)(i % QTK);
        float v = 0.f;
        if (n < 444) {
            if (k < 136) v = Wk[((size_t)l * E_ + k) * DK_ + n];
        } else if (n >= 448 && n < 892) {
            if (k >= 136 && k < E_) v = Wk[((size_t)l * E_ + k) * DK_ + (n - 448)];
        } else if (n == 896) {
            if (k < 136) v = bk[l * E_ + k];
        } else if (n == 897) {
            if (k >= 136 && k < E_) v = bk[l * E_ + k];
        }
        dst[i] = __float2half(v);
    }
}

// ---------------- Wov[l][m][h*448+j] = sum_d Wo[l][m][h*136+d] * Wv[l][h*136+d][j] ----
__global__ void build_wov(const float* __restrict__ Wo, const float* __restrict__ Wv)
{
    int m = blockIdx.x, h = blockIdx.y, l = blockIdx.z;
    __shared__ float wo[136];
    for (int d = threadIdx.x; d < 136; d += 128)
        wo[d] = Wo[((size_t)l * E_ + m) * E_ + h * 136 + d];
    __syncthreads();
    for (int j = threadIdx.x; j < 448; j += 128) {
        float s = 0.f;
        if (j < 444) {
            const float* wv = Wv + ((size_t)l * E_ + h * 136) * DK_ + j;
            #pragma unroll 4
            for (int d = 0; d < 136; d++) s += wo[d] * wv[(size_t)d * DK_];
        }
        g_Wov[((size_t)l * E_ + m) * CTW + h * 448 + j] = __float2half(s);
    }
}

// ---------------- b_ov[l] = Wo[l] @ bv[l] + bo[l] ----------------
__global__ void bov_kernel(const float* __restrict__ Wo, const float* __restrict__ bv,
                           const float* __restrict__ bo)
{
    int l = blockIdx.x, m = threadIdx.x;
    if (m < E_) {
        float s = bo[l * E_ + m];
        const float* w = Wo + ((size_t)l * E_ + m) * E_;
        for (int k = 0; k < E_; k++) s += w[k] * bv[l * E_ + k];
        g_bOV[l * E_ + m] = s;
    }
}

// ---------------- constant part of q: cos(b_time) @ Wq[:,172:].T + bq ----------------
__global__ void cq_kernel(const float* __restrict__ Wq, const float* __restrict__ bq,
                          const float* __restrict__ b_time)
{
    int l = blockIdx.x;
    int n = threadIdx.x;
    if (n < E_) {
        float s = bq[l*E_ + n];
        const float* w = Wq + (size_t)l*E_*E_ + (size_t)n*E_ + D_;
        #pragma unroll 4
        for (int j = 0; j < DT_; j++) s += cosf(b_time[j]) * w[j];
        g_CQ[l*E_ + n] = s;
    }
}

// ---------------- memory -> fp16 (stride QK, pads stay 0) ----------------
__global__ void memconv(const float* __restrict__ mem)
{
    long total = (long)NNODE * D_;
    for (long i = (long)blockIdx.x*blockDim.x + threadIdx.x; i < total;
         i += (long)gridDim.x * blockDim.x) {
        int r = (int)(i / D_);
        int k = (int)(i % D_);
        g_MEMh[(size_t)r * QK + k] = __float2half(mem[i]);
    }
}

// ---------------- fp16 row gather from g_MEMh (both stride QK) ----------------
__global__ void gather16(const int* __restrict__ idx, __half* __restrict__ dst, int rows)
{
    long total = (long)rows * 24;
    for (long i = (long)blockIdx.x*blockDim.x + threadIdx.x; i < total;
         i += (long)gridDim.x * blockDim.x) {
        int r = (int)(i / 24);
        int s = (int)(i % 24);
        ((uint4*)(dst + (size_t)r * QK))[s] =
            ((const uint4*)(g_MEMh + (size_t)idx[r] * QK))[s];
    }
}

// ---------------- copy SRC into MLP-input cols [272, 444) of g_Afull ----------------
__global__ void copy_src(int rows)
{
    long total = (long)rows * D_;
    for (long i = (long)blockIdx.x*blockDim.x + threadIdx.x; i < total;
         i += (long)gridDim.x * blockDim.x) {
        int r = (int)(i / D_);
        int k = (int)(i % D_);
        g_Afull[(size_t)r * KPAD + E_ + k] = g_SRCh[(size_t)r * QK + k];
    }
}

// ============================================================================
// fused attention: block per query. kv = [mem(172)|cos(100)|edge(172)|pad4].
// scores_h = (q~_h . kv + c_h)/sqrt(136), softmax w/ neighbor==0 mask,
// ctx_h = sum_n a_hn kv_n  ->  CTX[r] = [ctx0(448)|ctx1(448)] fp16.
// ============================================================================
template<int GATHER>
__global__ __launch_bounds__(128)
void fused_attn(const __half* __restrict__ memh, int mstride,
                const int* __restrict__ nbrs,
                const float* __restrict__ edgef,
                const int* __restrict__ eidx,
                const float* __restrict__ etime,
                const float* __restrict__ ts, int ts_div,
                const float* __restrict__ w_time, const float* __restrict__ b_time,
                const __half* __restrict__ QT,
                __half* __restrict__ CTX, int* __restrict__ AM, int R)
{
    __shared__ __half skv[NN][448];
    __shared__ float sc[2][NN];
    __shared__ float aw[2][NN];

    int r = blockIdx.x;
    if (r >= R) return;
    int tid = threadIdx.x, lane = tid & 31, w = tid >> 5;
    float tsr = ts[r / ts_div];
    const long kvbase = (long)r * NN;

    // Phase A: build kv tile in shared
    for (int idx = tid; idx < NN * 448; idx += 128) {
        int n = idx / 448, j = idx - n * 448;
        long kvrow = kvbase + n;
        float v;
        if (j < D_) {
            long src = GATHER ? (long)nbrs[kvrow] : kvrow;
            v = __half2float(memh[src * mstride + j]);
        } else if (j < E_) {
            int q = j - D_;
            float dt = tsr - etime[kvrow];
            v = __cosf(dt * w_time[q] + b_time[q]);
        } else if (j < DK_) {
            v = edgef[(size_t)eidx[kvrow] * D_ + (j - E_)];
        } else v = 0.f;
        skv[n][j] = __float2half(v);
    }
    __syncthreads();

    // Phase B: scores (40 (n,h) pairs over 4 warps)
    const __half* qtr = QT + (size_t)r * QTW;
    float q0[14], q1[14];
    #pragma unroll
    for (int i = 0; i < 14; ++i) {
        int j = lane + i * 32;
        q0[i] = __half2float(qtr[j]);
        q1[i] = __half2float(qtr[448 + j]);
    }
    for (int p = w; p < 2 * NN; p += 4) {
        int n = p >> 1, h = p & 1;
        float s = 0.f;
        #pragma unroll
        for (int i = 0; i < 14; ++i) {
            float kv = __half2float(skv[n][lane + i * 32]);
            s += (h ? q1[i] : q0[i]) * kv;
        }
        #pragma unroll
        for (int o = 16; o; o >>= 1) s += __shfl_xor_sync(0xffffffffu, s, o);
        if (lane == 0) sc[h][n] = s;
    }
    __syncthreads();

    // Phase C: masked softmax per head (threads 0,1)
    if (tid < 2) {
        int h = tid;
        float ch = __half2float(qtr[896 + h]);
        const float scale = rsqrtf(136.f);
        float v[NN];
        float mx = -3.4e38f;
        int allm = 1;
        #pragma unroll
        for (int n = 0; n < NN; n++) {
            int masked = (nbrs[kvbase + n] == 0);
            float s = masked ? -1e9f : (sc[h][n] + ch) * scale;
            if (!masked) allm = 0;
            v[n] = s;
            mx = fmaxf(mx, s);
        }
        float ssum = 0.f;
        #pragma unroll
        for (int n = 0; n < NN; n++) { float e = __expf(v[n] - mx); v[n] = e; ssum += e; }
        float inv = 1.f / ssum;
        #pragma unroll
        for (int n = 0; n < NN; n++) aw[h][n] = v[n] * inv;
        if (h == 0) AM[r] = allm;
    }
    __syncthreads();

    // Phase D: per-head context aggregation
    for (int j = tid; j < 448; j += 128) {
        float c0 = 0.f, c1 = 0.f;
        #pragma unroll
        for (int n = 0; n < NN; n++) {
            float kv = __half2float(skv[n][j]);
            c0 += aw[0][n] * kv;
            c1 += aw[1][n] * kv;
        }
        CTX[(size_t)r * CTW + j]       = __float2half(c0);
        CTX[(size_t)r * CTW + 448 + j] = __float2half(c1);
    }
}

// ---------------- host helpers ----------------
static void launch_hgemm_h(const __half* A, int lda, const __half* W, const float* bias,
                           const int* rz, __half* C, int ldc, int M, int N, int K, int relu)
{
    dim3 grid((N + 95)/96, (M + 127)/128);
    hgemm<1><<<grid, 256, HG_SMEM>>>(A, lda, W, bias, rz, (void*)C, ldc, M, N, K, relu);
}
static void launch_hgemm_f(const __half* A, int lda, const __half* W, const float* bias,
                           const int* rz, float* C, int ldc, int M, int N, int K, int relu)
{
    dim3 grid((N + 95)/96, (M + 127)/128);
    hgemm<0><<<grid, 256, HG_SMEM>>>(A, lda, W, bias, rz, (void*)C, ldc, M, N, K, relu);
}

extern "C" void kernel_launch(void* const* d_in, const int* in_sizes, int n_in,
                              void* d_out, int out_size)
{
    const float* memory = (const float*)d_in[0];
    const float* edgef  = (const float*)d_in[1];
    const int*   srcn   = (const int*)  d_in[2];
    const float* ts     = (const float*)d_in[3];
    const int*   nb1    = (const int*)  d_in[4];
    const int*   ei1    = (const int*)  d_in[5];
    const float* et1    = (const float*)d_in[6];
    const int*   nb2    = (const int*)  d_in[7];
    const int*   ei2    = (const int*)  d_in[8];
    const float* et2    = (const float*)d_in[9];
    const float* w_time = (const float*)d_in[10];
    const float* b_time = (const float*)d_in[11];
    const float* Wq = (const float*)d_in[12];
    const float* bq = (const float*)d_in[13];
    const float* Wk = (const float*)d_in[14];
    const float* bk = (const float*)d_in[15];
    const float* Wv = (const float*)d_in[16];
    const float* bv = (const float*)d_in[17];
    const float* Wo = (const float*)d_in[18];
    const float* bo = (const float*)d_in[19];
    const float* W1 = (const float*)d_in[20];
    const float* b1 = (const float*)d_in[21];
    const float* W2 = (const float*)d_in[22];
    const float* b2 = (const float*)d_in[23];
    float* out = (float*)d_out;

    __half *pMEMh, *pSRCh, *pQh, *pQT, *pCTX, *pAfull, *pHh, *pEMBh;
    __half *pWqh, *pWqk, *pWov, *pW1h, *pW2h;
    float *pbOV, *pCQ, *pZero;
    int* pAM;
    cudaGetSymbolAddress((void**)&pMEMh,  g_MEMh);
    cudaGetSymbolAddress((void**)&pSRCh,  g_SRCh);
    cudaGetSymbolAddress((void**)&pQh,    g_Qh);
    cudaGetSymbolAddress((void**)&pQT,    g_QTh);
    cudaGetSymbolAddress((void**)&pCTX,   g_CTX);
    cudaGetSymbolAddress((void**)&pAfull, g_Afull);
    cudaGetSymbolAddress((void**)&pHh,    g_Hh);
    cudaGetSymbolAddress((void**)&pEMBh,  g_EMBh);
    cudaGetSymbolAddress((void**)&pWqh,   g_Wqh);
    cudaGetSymbolAddress((void**)&pWqk,   g_Wqk);
    cudaGetSymbolAddress((void**)&pWov,   g_Wov);
    cudaGetSymbolAddress((void**)&pW1h,   g_W1h);
    cudaGetSymbolAddress((void**)&pW2h,   g_W2h);
    cudaGetSymbolAddress((void**)&pbOV,   g_bOV);
    cudaGetSymbolAddress((void**)&pCQ,    g_CQ);
    cudaGetSymbolAddress((void**)&pZero,  g_zero);
    cudaGetSymbolAddress((void**)&pAM,    g_AM);

    cudaFuncSetAttribute((const void*)hgemm<1>, cudaFuncAttributeMaxDynamicSharedMemorySize, HG_SMEM);
    cudaFuncSetAttribute((const void*)hgemm<0>, cudaFuncAttributeMaxDynamicSharedMemorySize, HG_SMEM);

    const size_t WQs = (size_t)E_*QK, WQKs = (size_t)WQKR*QTK, WOVs = (size_t)E_*CTW,
                 W1s = (size_t)D_*KPAD, W2s = (size_t)D_*QK;

    // ---- weight preparation ----
    convert_all<<<dim3(64, 6), 256>>>(Wq, W1, W2);
    build_wqk<<<dim3(256, 2), 256>>>(Wk, bk);
    build_wov<<<dim3(E_, 2, 2), 128>>>(Wo, Wv);
    bov_kernel<<<2, E_>>>(Wo, bv, bo);
    cq_kernel<<<2, E_>>>(Wq, bq, b_time);
    memconv<<<512, 256>>>(memory);

    // ================= Layer 1 =================
    gather16<<<(R1*24 + 255)/256, 256>>>(nb1, pSRCh, R1);
    launch_hgemm_h(pSRCh, QK, pWqh, pCQ, nullptr, pQh, E_, R1, E_, QK, 0);
    launch_hgemm_h(pQh, E_, pWqk, pZero, nullptr, pQT, QTW, R1, QTN, QTK, 0);

    fused_attn<1><<<R1, 128>>>(pMEMh, QK, nb2, edgef, ei2, et2, ts, NN,
                               w_time, b_time, pQT, pCTX, pAM, R1);

    launch_hgemm_h(pCTX, CTW, pWov, pbOV, pAM, pAfull, KPAD, R1, E_, CTW, 0);
    copy_src<<<(R1*D_ + 255)/256, 256>>>(R1);
    launch_hgemm_h(pAfull, KPAD, pW1h, b1, nullptr, pHh, QK, R1, D_, KPAD, 1);
    launch_hgemm_h(pHh, QK, pW2h, b2, nullptr, pEMBh, D_, R1, D_, QK, 0);

    // ================= Layer 2 =================
    gather16<<<(NB*24 + 255)/256, 256>>>(srcn, pSRCh, NB);
    launch_hgemm_h(pSRCh, QK, pWqh + WQs, pCQ + E_, nullptr, pQh, E_, NB, E_, QK, 0);
    launch_hgemm_h(pQh, E_, pWqk + WQKs, pZero, nullptr, pQT, QTW, NB, QTN, QTK, 0);

    fused_attn<0><<<NB, 128>>>(pEMBh, D_, nb1, edgef, ei1, et1, ts, 1,
                               w_time, b_time, pQT, pCTX, pAM, NB);

    launch_hgemm_h(pCTX, CTW, pWov + WOVs, pbOV + E_, pAM, pAfull, KPAD, NB, E_, CTW, 0);
    copy_src<<<(NB*D_ + 255)/256, 256>>>(NB);
    launch_hgemm_h(pAfull, KPAD, pW1h + W1s, b1 + D_, nullptr, pHh, QK, NB, D_, KPAD, 1);
    launch_hgemm_f(pHh, QK, pW2h + W2s, b2 + D_, nullptr, out, D_, NB, D_, QK, 0);
}